// round 6
// baseline (speedup 1.0000x reference)
#include <cuda_runtime.h>
#include <cstdint>

#define NN 50000
#define EE 100000
#define KNODE 544          /* 512 x-dims + 10 PE dims + 22 zero pad */

#define BM 128
#define BN 256
#define BK 32
#define NSTAGE 4
#define ROWSTRIDE 36                     /* 32 floats + 4 pad; 144B rows, LDSM conflict-free */
#define A_FLOATS (BM * ROWSTRIDE)        /* 4608 */
#define STAGE_F ((BM + BN) * ROWSTRIDE)  /* 13824 floats = 55296 B */
#define SMEM_DYN (NSTAGE * STAGE_F * 4)  /* 221184 B */

// ---------------- scratch (device globals; no runtime allocations) ----------
__device__ float g_G[(size_t)NN * 1024];        // [n][0:512]=src-proj, [512:1024]=dst-proj
__device__ float g_Xp[(size_t)NN * KNODE];      // prepared node features (tf32-rna)
__device__ float g_WnodeT[1024 * KNODE];        // [out j][k] K-major, tf32-rna
__device__ float g_WqaT[512 * 1024];            // [out j][k] K-major, tf32-rna
__device__ float g_p[NN * 10];
__device__ float g_deg_in[NN];
__device__ float g_deg_out[NN];

// ---------------- helpers ---------------------------------------------------
__device__ __forceinline__ float tf32r(float f) {
    unsigned u;
    asm("cvt.rna.tf32.f32 %0, %1;" : "=r"(u) : "f"(f));
    return __uint_as_float(u);
}
__device__ __forceinline__ uint32_t smem_u32(const void* p) {
    return (uint32_t)__cvta_generic_to_shared(p);
}
__device__ __forceinline__ void cp16(void* sdst, const void* gsrc, int bytes) {
    unsigned d = (unsigned)__cvta_generic_to_shared(sdst);
    asm volatile("cp.async.cg.shared.global [%0], [%1], 16, %2;"
                 :: "r"(d), "l"(gsrc), "r"(bytes));
}
__device__ __forceinline__ void cp_commit() {
    asm volatile("cp.async.commit_group;" ::: "memory");
}
__device__ __forceinline__ void cp_wait(int rem) {
    if (rem >= 2)      asm volatile("cp.async.wait_group 2;" ::: "memory");
    else if (rem == 1) asm volatile("cp.async.wait_group 1;" ::: "memory");
    else               asm volatile("cp.async.wait_group 0;" ::: "memory");
}

__device__ __forceinline__ void mma_tf32(float* c, const uint32_t* a, const uint32_t* b) {
    asm volatile(
        "mma.sync.aligned.m16n8k8.row.col.f32.tf32.tf32.f32 "
        "{%0,%1,%2,%3}, {%4,%5,%6,%7}, {%8,%9}, {%0,%1,%2,%3};\n"
        : "+f"(c[0]), "+f"(c[1]), "+f"(c[2]), "+f"(c[3])
        : "r"(a[0]), "r"(a[1]), "r"(a[2]), "r"(a[3]), "r"(b[0]), "r"(b[1]));
}

#define LDSM4(d0, d1, d2, d3, addr) \
    asm volatile("ldmatrix.sync.aligned.m8n8.x4.shared.b16 {%0,%1,%2,%3}, [%4];" \
                 : "=r"(d0), "=r"(d1), "=r"(d2), "=r"(d3) : "r"(addr))

// ---------------- prep: pack & tf32-round both weight blocks (transposed) ----
// W1 row map: q:0..511 | src.x:512..1023 | src.pe:1024..1033 | attr:1034..1545
//             dst.x:1546..2057 | dst.pe:2058..2067
__global__ void prep_w(const float* __restrict__ W1) {
    int idx = blockIdx.x * 256 + threadIdx.x;
    if (idx < 1024 * KNODE) {
        int j = idx / KNODE, k = idx % KNODE;
        bool hi = (j >= 512); int jj = j & 511;
        float v = 0.f;
        if (k < 512)      v = W1[(size_t)((hi ? 1546 : 512) + k) * 512 + jj];
        else if (k < 522) v = W1[(size_t)((hi ? 2058 : 1024) + (k - 512)) * 512 + jj];
        g_WnodeT[idx] = tf32r(v);
    } else {
        int i2 = idx - 1024 * KNODE;
        if (i2 >= 512 * 1024) return;
        int j = i2 >> 10, k = i2 & 1023;
        int row = (k < 512) ? k : (1034 + (k - 512));
        g_WqaT[i2] = tf32r(W1[(size_t)row * 512 + j]);
    }
}

__global__ void init_all(const float* __restrict__ topic,
                         const float* __restrict__ b2, float* __restrict__ out) {
    int idx = blockIdx.x * 256 + threadIdx.x;
    if (idx < NN) {
        g_p[idx * 10 + 0] = topic[idx * 2 + 0];
        g_p[idx * 10 + 1] = topic[idx * 2 + 1];
        #pragma unroll
        for (int c = 2; c < 10; ++c) g_p[idx * 10 + c] = 0.f;
        g_deg_in[idx] = 0.f;
        g_deg_out[idx] = 0.f;
    }
    if (idx < EE) out[idx] = b2[0];
}

__global__ void conv1(const int* __restrict__ srcI, const int* __restrict__ dstI) {
    int e = blockIdx.x * 256 + threadIdx.x;
    if (e >= EE) return;
    int s = srcI[e], d = dstI[e];
    atomicAdd(&g_p[d * 10 + 2], g_p[s * 10 + 0]);
    atomicAdd(&g_p[d * 10 + 3], g_p[s * 10 + 1]);
    atomicAdd(&g_p[s * 10 + 6], g_p[d * 10 + 0]);
    atomicAdd(&g_p[s * 10 + 7], g_p[d * 10 + 1]);
    atomicAdd(&g_deg_in[d], 1.f);
    atomicAdd(&g_deg_out[s], 1.f);
}

__global__ void conv2(const int* __restrict__ srcI, const int* __restrict__ dstI) {
    int e = blockIdx.x * 256 + threadIdx.x;
    if (e >= EE) return;
    int s = srcI[e], d = dstI[e];
    float inv_s = 1.f / fmaxf(g_deg_in[s], 1.f);
    float inv_d = 1.f / fmaxf(g_deg_out[d], 1.f);
    atomicAdd(&g_p[d * 10 + 4], g_p[s * 10 + 2] * inv_s);
    atomicAdd(&g_p[d * 10 + 5], g_p[s * 10 + 3] * inv_s);
    atomicAdd(&g_p[s * 10 + 8], g_p[d * 10 + 6] * inv_d);
    atomicAdd(&g_p[s * 10 + 9], g_p[d * 10 + 7] * inv_d);
}

__global__ void prep_xp(const float* __restrict__ x, const float* __restrict__ ne) {
    int n = (blockIdx.x * 256 + threadIdx.x) >> 5;
    int lane = threadIdx.x & 31;
    if (n >= NN) return;
    const float4* xr = (const float4*)(x + (size_t)n * 512);
    float4 v[4];
    bool nz = false;
    #pragma unroll
    for (int i = 0; i < 4; ++i) {
        v[i] = xr[i * 32 + lane];
        nz |= (v[i].x != 0.f) | (v[i].y != 0.f) | (v[i].z != 0.f) | (v[i].w != 0.f);
    }
    nz = __any_sync(0xffffffffu, nz);
    float* dst = g_Xp + (size_t)n * KNODE;
    const float4* nr = (const float4*)ne;
    #pragma unroll
    for (int i = 0; i < 4; ++i) {
        float4 w = nz ? v[i] : nr[i * 32 + lane];
        float4 r;
        r.x = tf32r(w.x); r.y = tf32r(w.y); r.z = tf32r(w.z); r.w = tf32r(w.w);
        *(float4*)(dst + (i * 32 + lane) * 4) = r;
    }
    if (lane < 10) {
        float di = fmaxf(g_deg_in[n], 1.f);
        float dv = fmaxf(g_deg_out[n], 1.f);
        float val = g_p[n * 10 + lane];
        if (lane >= 2 && lane < 6) val /= di;
        else if (lane >= 6) val /= dv;
        dst[512 + lane] = tf32r(val);
    } else {
        dst[512 + lane] = 0.f;
    }
}

// ---------------- GEMM core shared pieces ------------------------------------
extern __shared__ float dynsmem[];

// Fragment loads for one k-step (ks): A 4x ldmatrix.x4, B 4x ldmatrix.x4.
// a[mf][4], b[nf][2] register layouts match mma.m16n8k8 exactly.
#define LOAD_FRAGS(buf, ks)                                                     \
    do {                                                                        \
        _Pragma("unroll")                                                       \
        for (int mf = 0; mf < 4; ++mf) {                                        \
            uint32_t ad = Abase + (uint32_t)(((wm * 64 + mf * 16) * ROWSTRIDE   \
                                              + (ks) * 8) * 4) + laneoff;       \
            LDSM4(a[buf][mf][0], a[buf][mf][1], a[buf][mf][2], a[buf][mf][3], ad); \
        }                                                                       \
        _Pragma("unroll")                                                       \
        for (int h = 0; h < 4; ++h) {                                           \
            uint32_t q0, q1, q2, q3;                                            \
            uint32_t bd = Bbase + (uint32_t)(((wn * 64 + h * 16) * ROWSTRIDE    \
                                              + (ks) * 8) * 4) + laneoff;       \
            LDSM4(q0, q1, q2, q3, bd);                                          \
            b[buf][2 * h][0] = q0; b[buf][2 * h + 1][0] = q1;                   \
            b[buf][2 * h][1] = q2; b[buf][2 * h + 1][1] = q3;                   \
        }                                                                       \
    } while (0)

#define MMA_ALL(buf)                                                            \
    do {                                                                        \
        _Pragma("unroll")                                                       \
        for (int mf = 0; mf < 4; ++mf)                                          \
            _Pragma("unroll")                                                   \
            for (int nf = 0; nf < 8; ++nf)                                      \
                mma_tf32(acc[mf][nf], a[buf][mf], b[buf][nf]);                  \
    } while (0)

// ---------------- node GEMM: g_G = g_Xp @ g_WnodeT^T --------------------------
__global__ __launch_bounds__(256, 1) void node_gemm() {
    const int tid = threadIdx.x, warp = tid >> 5, lane = tid & 31;
    const int wm = warp & 1, wn = warp >> 1;
    const int g = lane >> 2, t = lane & 3;
    const int m0 = blockIdx.x * BM, n0 = blockIdx.y * BN;
    const int KT = KNODE / BK;  // 17
    // lane-constant ldmatrix offset: row = lane&15, kcol = (lane>>4)*4
    const uint32_t laneoff = (uint32_t)(((lane & 15) * ROWSTRIDE + (lane >> 4) * 4) * 4);

    float acc[4][8][4];
    #pragma unroll
    for (int i = 0; i < 4; ++i)
        #pragma unroll
        for (int j = 0; j < 8; ++j)
            #pragma unroll
            for (int k = 0; k < 4; ++k) acc[i][j][k] = 0.f;

    auto load_tile = [&](int stage, int kt) {
        float* As = dynsmem + stage * STAGE_F;
        float* Bs = As + A_FLOATS;
        int kb = kt * BK;
        #pragma unroll
        for (int i = 0; i < 4; ++i) {
            int id = i * 256 + tid;
            int row = id >> 3, ch = id & 7;
            int n = m0 + row;
            cp16(As + row * ROWSTRIDE + ch * 4,
                 g_Xp + (size_t)n * KNODE + kb + ch * 4, (n < NN) ? 16 : 0);
        }
        #pragma unroll
        for (int i = 0; i < 8; ++i) {
            int id = i * 256 + tid;
            int row = id >> 3, ch = id & 7;
            cp16(Bs + row * ROWSTRIDE + ch * 4,
                 g_WnodeT + (size_t)(n0 + row) * KNODE + kb + ch * 4, 16);
        }
        cp_commit();
    };

    load_tile(0, 0);
    load_tile(1, 1);

    for (int kt = 0; kt < KT; ++kt) {
        if (kt + 2 < KT) load_tile((kt + 2) & 3, kt + 2);
        cp_wait(KT - 1 - kt);
        __syncthreads();

        const float* stg = dynsmem + (kt & 3) * STAGE_F;
        const uint32_t Abase = smem_u32(stg);
        const uint32_t Bbase = smem_u32(stg + A_FLOATS);
        uint32_t a[2][4][4], b[2][8][2];
        LOAD_FRAGS(0, 0);
        #pragma unroll
        for (int ks = 0; ks < 4; ++ks) {
            int cb = ks & 1;
            if (ks < 3) LOAD_FRAGS(cb ^ 1, ks + 1);
            MMA_ALL(cb);
        }
    }

    #pragma unroll
    for (int mf = 0; mf < 4; ++mf) {
        #pragma unroll
        for (int half = 0; half < 2; ++half) {
            int r = wm * 64 + mf * 16 + g + half * 8;
            int n = m0 + r;
            if (n < NN) {
                float* Gp = g_G + (size_t)n * 1024 + n0;
                #pragma unroll
                for (int nf = 0; nf < 8; ++nf) {
                    int cj = wn * 64 + nf * 8 + 2 * t;
                    *(float2*)&Gp[cj] = make_float2(acc[mf][nf][half * 2 + 0],
                                                    acc[mf][nf][half * 2 + 1]);
                }
            }
        }
    }
}

// ---------------- edge GEMM + fused gather/relu/W2 epilogue ------------------
__global__ __launch_bounds__(256, 1) void edge_gemm(
    const float* __restrict__ q_emb, const float* __restrict__ edge_attr,
    const int* __restrict__ srcI, const int* __restrict__ dstI,
    const float* __restrict__ b1, const float* __restrict__ W2,
    float* __restrict__ out)
{
    __shared__ float sB1[BN];
    __shared__ float sW2[BN];

    const int tid = threadIdx.x, warp = tid >> 5, lane = tid & 31;
    const int wm = warp & 1, wn = warp >> 1;
    const int g = lane >> 2, t = lane & 3;
    const int m0 = blockIdx.x * BM, n0 = blockIdx.y * BN;
    const int KT = 1024 / BK;  // 32
    const uint32_t laneoff = (uint32_t)(((lane & 15) * ROWSTRIDE + (lane >> 4) * 4) * 4);

    sB1[tid] = b1[n0 + tid];
    sW2[tid] = W2[n0 + tid];

    float acc[4][8][4];
    #pragma unroll
    for (int i = 0; i < 4; ++i)
        #pragma unroll
        for (int j = 0; j < 8; ++j)
            #pragma unroll
            for (int k = 0; k < 4; ++k) acc[i][j][k] = 0.f;

    auto load_tile = [&](int stage, int kt) {
        float* As = dynsmem + stage * STAGE_F;
        float* Bs = As + A_FLOATS;
        int kb = kt * BK;
        #pragma unroll
        for (int i = 0; i < 4; ++i) {
            int id = i * 256 + tid;
            int row = id >> 3, ch = id & 7;
            int e = m0 + row;
            int kg = kb + ch * 4;
            const float* src = (kg < 512) ? q_emb + (size_t)e * 512 + kg
                                          : edge_attr + (size_t)e * 512 + (kg - 512);
            cp16(As + row * ROWSTRIDE + ch * 4, src, (e < EE) ? 16 : 0);
        }
        #pragma unroll
        for (int i = 0; i < 8; ++i) {
            int id = i * 256 + tid;
            int row = id >> 3, ch = id & 7;
            cp16(Bs + row * ROWSTRIDE + ch * 4,
                 g_WqaT + (size_t)(n0 + row) * 1024 + kb + ch * 4, 16);
        }
        cp_commit();
    };

    load_tile(0, 0);
    load_tile(1, 1);

    for (int kt = 0; kt < KT; ++kt) {
        if (kt + 2 < KT) load_tile((kt + 2) & 3, kt + 2);
        cp_wait(KT - 1 - kt);
        __syncthreads();

        const float* stg = dynsmem + (kt & 3) * STAGE_F;
        const uint32_t Abase = smem_u32(stg);
        const uint32_t Bbase = smem_u32(stg + A_FLOATS);
        uint32_t a[2][4][4], b[2][8][2];
        LOAD_FRAGS(0, 0);
        #pragma unroll
        for (int ks = 0; ks < 4; ++ks) {
            int cb = ks & 1;
            if (ks < 3) LOAD_FRAGS(cb ^ 1, ks + 1);
            MMA_ALL(cb);
        }
    }

    // epilogue: z = acc + b1 + G_src[s] + G_dst[d]; relu; dot W2; atomic add
    #pragma unroll
    for (int mf = 0; mf < 4; ++mf) {
        #pragma unroll
        for (int half = 0; half < 2; ++half) {
            int r = wm * 64 + mf * 16 + g + half * 8;
            int e = m0 + r;
            float rowsum = 0.f;
            if (e < EE) {
                int s = srcI[e], d = dstI[e];
                const float* Gs = g_G + (size_t)s * 1024 + n0;
                const float* Gd = g_G + (size_t)d * 1024 + 512 + n0;
                #pragma unroll
                for (int nf = 0; nf < 8; ++nf) {
                    int cj = wn * 64 + nf * 8 + 2 * t;
                    float2 gs = *(const float2*)&Gs[cj];
                    float2 gd = *(const float2*)&Gd[cj];
                    float z0 = acc[mf][nf][half * 2 + 0] + sB1[cj] + gs.x + gd.x;
                    float z1 = acc[mf][nf][half * 2 + 1] + sB1[cj + 1] + gs.y + gd.y;
                    rowsum = fmaf(fmaxf(z0, 0.f), sW2[cj], rowsum);
                    rowsum = fmaf(fmaxf(z1, 0.f), sW2[cj + 1], rowsum);
                }
            }
            rowsum += __shfl_xor_sync(0xffffffffu, rowsum, 1);
            rowsum += __shfl_xor_sync(0xffffffffu, rowsum, 2);
            if (t == 0 && e < EE) atomicAdd(out + e, rowsum);
        }
    }
}

// ---------------- launch ------------------------------------------------------
extern "C" void kernel_launch(void* const* d_in, const int* in_sizes, int n_in,
                              void* d_out, int out_size) {
    const float* x     = (const float*)d_in[0];
    const int*   ei    = (const int*)d_in[1];
    const float* attr  = (const float*)d_in[2];
    const float* topic = (const float*)d_in[3];
    const float* qemb  = (const float*)d_in[4];
    const float* ne    = (const float*)d_in[5];
    const float* W1    = (const float*)d_in[6];
    const float* b1    = (const float*)d_in[7];
    const float* W2    = (const float*)d_in[8];
    const float* b2    = (const float*)d_in[9];
    float* out = (float*)d_out;
    const int* srcI = ei;
    const int* dstI = ei + EE;

    cudaFuncSetAttribute(node_gemm, cudaFuncAttributeMaxDynamicSharedMemorySize, SMEM_DYN);
    cudaFuncSetAttribute(edge_gemm, cudaFuncAttributeMaxDynamicSharedMemorySize, SMEM_DYN);

    const int WTOT = 1024 * KNODE + 512 * 1024;
    prep_w<<<(WTOT + 255) / 256, 256>>>(W1);
    init_all<<<(EE + 255) / 256, 256>>>(topic, b2, out);
    conv1<<<(EE + 255) / 256, 256>>>(srcI, dstI);
    conv2<<<(EE + 255) / 256, 256>>>(srcI, dstI);
    prep_xp<<<(NN * 32 + 255) / 256, 256>>>(x, ne);
    node_gemm<<<dim3((NN + BM - 1) / BM, 1024 / BN), 256, SMEM_DYN>>>();
    edge_gemm<<<dim3((EE + BM - 1) / BM, 512 / BN), 256, SMEM_DYN>>>(
        qemb, attr, srcI, dstI, b1, W2, out);
}